// round 9
// baseline (speedup 1.0000x reference)
#include <cuda_runtime.h>
#include <cstdint>
#include <math_constants.h>

#define B_ 32
#define T_ 4096
#define E_ 512
#define R_ 64
#define K_ 512

// scratch (no allocations allowed)
__device__ float g_c[7 * B_ * T_];   // c_j[b,t] per conv tap
__device__ int   g_idx[B_ * K_];     // ascending selected indices per batch

typedef unsigned long long ull;

__device__ __forceinline__ ull pk2(float lo, float hi) {
    ull r;
    asm("mov.b64 %0, {%1, %2};" : "=l"(r) : "f"(lo), "f"(hi));
    return r;
}
__device__ __forceinline__ void fma2(ull& d, ull a, ull b) {
    asm("fma.rn.f32x2 %0, %1, %2, %0;" : "+l"(d) : "l"(a), "l"(b));
}

// ---------------------------------------------------------------------------
// k1: GEMM (131072x512 @ 512x64) + bias + exact GELU + folded LayerNorm+conv
// tile 128m x 64n, 256 threads, 4m x 8n per thread (fma2 packed along n).
// e-block = 16, ping-pong smem (1 sync/e-block), 2 CTAs/SM.
// Crossbar budget: per warp-el 3 wavefronts vs 32 fma-pipe cycles -> fma-bound.
// ---------------------------------------------------------------------------
#define EB 16
#define XS_STR 132
#define WS_STR 68
__global__ __launch_bounds__(256, 2) void k1_gemm(
    const float* __restrict__ emb, const float* __restrict__ W1,
    const float* __restrict__ b1,  const float* __restrict__ ln_g,
    const float* __restrict__ ln_b, const float* __restrict__ conv_w)
{
    __shared__ float Xs[2 * EB * XS_STR];   // 16.9 KB
    __shared__ float Ws[2 * EB * WS_STR];   // 8.7 KB
    __shared__ float gw_s[7 * 64];
    __shared__ float b1_s[64];
    __shared__ float sG[7], sS[7];

    const int tid = threadIdx.x;
    const int b   = blockIdx.x >> 5;
    const int t0  = (blockIdx.x & 31) << 7;

    if (tid < 64) b1_s[tid] = b1[tid];
    for (int i = tid; i < 448; i += 256) gw_s[i] = ln_g[i & 63] * conv_w[i];
    __syncthreads();
    if (tid < 7) {
        float G = 0.f, S = 0.f;
        #pragma unroll 8
        for (int r = 0; r < 64; r++) {
            G += gw_s[tid * 64 + r];
            S += ln_b[r] * conv_w[tid * 64 + r];
        }
        sG[tid] = G; sS[tid] = S;
    }

    // thread tile: 4 m-rows (m0..m0+3) x 8 n-cols (n0..n0+7), acc packed by n-pair
    const int x  = tid & 7, y = tid >> 3;
    const int m0 = y << 2,  n0 = x << 3;
    ull acc[4][4];                         // [m][n-pair]
    #pragma unroll
    for (int i = 0; i < 4; i++)
        #pragma unroll
        for (int j = 0; j < 4; j++) acc[i][j] = 0ull;

    const float* embB = emb + (size_t)(b * T_ + t0) * E_;

    // staging coordinates (e-block = 16)
    int xm[2], xe4[2];
    #pragma unroll
    for (int li = 0; li < 2; li++) {
        int L = tid + (li << 8);
        xm[li]  = L >> 2;            // 0..127
        xe4[li] = (L & 3) << 2;      // 0,4,8,12
    }
    const int wel = tid >> 4;        // 0..15
    const int wn4 = (tid & 15) << 2; // 0..60

    float4 xa[2], wb;
    #pragma unroll
    for (int li = 0; li < 2; li++)
        xa[li] = *(const float4*)&embB[(size_t)xm[li] * E_ + xe4[li]];
    wb = *(const float4*)&W1[(size_t)wel * 64 + wn4];

    // store e-block 0 into buffer 0
    #pragma unroll
    for (int li = 0; li < 2; li++) {
        Xs[(xe4[li] + 0) * XS_STR + xm[li]] = xa[li].x;
        Xs[(xe4[li] + 1) * XS_STR + xm[li]] = xa[li].y;
        Xs[(xe4[li] + 2) * XS_STR + xm[li]] = xa[li].z;
        Xs[(xe4[li] + 3) * XS_STR + xm[li]] = xa[li].w;
    }
    *(float4*)&Ws[wel * WS_STR + wn4] = wb;
    __syncthreads();

    const int NEB = E_ / EB;   // 32
    for (int eb = 0; eb < NEB; eb++) {
        const float* Xb = Xs + (eb & 1) * (EB * XS_STR);
        const float* Wb = Ws + (eb & 1) * (EB * WS_STR);

        if (eb + 1 < NEB) {      // prefetch next e-block (latency hidden)
            int e0 = (eb + 1) * EB;
            #pragma unroll
            for (int li = 0; li < 2; li++)
                xa[li] = *(const float4*)&embB[(size_t)xm[li] * E_ + e0 + xe4[li]];
            wb = *(const float4*)&W1[(size_t)(e0 + wel) * 64 + wn4];
        }

        #pragma unroll
        for (int el = 0; el < EB; el++) {
            float4 a4 = *(const float4*)&Xb[el * XS_STR + m0];      // 4 m-rows
            ull am0 = pk2(a4.x, a4.x);
            ull am1 = pk2(a4.y, a4.y);
            ull am2 = pk2(a4.z, a4.z);
            ull am3 = pk2(a4.w, a4.w);
            ulonglong2 wA = *(const ulonglong2*)&Wb[el * WS_STR + n0];      // n0..n0+3
            ulonglong2 wB = *(const ulonglong2*)&Wb[el * WS_STR + n0 + 4];  // n0+4..n0+7
            fma2(acc[0][0], am0, wA.x); fma2(acc[0][1], am0, wA.y);
            fma2(acc[0][2], am0, wB.x); fma2(acc[0][3], am0, wB.y);
            fma2(acc[1][0], am1, wA.x); fma2(acc[1][1], am1, wA.y);
            fma2(acc[1][2], am1, wB.x); fma2(acc[1][3], am1, wB.y);
            fma2(acc[2][0], am2, wA.x); fma2(acc[2][1], am2, wA.y);
            fma2(acc[2][2], am2, wB.x); fma2(acc[2][3], am2, wB.y);
            fma2(acc[3][0], am3, wA.x); fma2(acc[3][1], am3, wA.y);
            fma2(acc[3][2], am3, wB.x); fma2(acc[3][3], am3, wB.y);
        }

        if (eb + 1 < NEB) {
            float* Xn = Xs + ((eb + 1) & 1) * (EB * XS_STR);
            float* Wn = Ws + ((eb + 1) & 1) * (EB * WS_STR);
            #pragma unroll
            for (int li = 0; li < 2; li++) {
                Xn[(xe4[li] + 0) * XS_STR + xm[li]] = xa[li].x;
                Xn[(xe4[li] + 1) * XS_STR + xm[li]] = xa[li].y;
                Xn[(xe4[li] + 2) * XS_STR + xm[li]] = xa[li].z;
                Xn[(xe4[li] + 3) * XS_STR + xm[li]] = xa[li].w;
            }
            *(float4*)&Wn[wel * WS_STR + wn4] = wb;
            __syncthreads();
        }
    }
    __syncthreads();

    // tail: GELU, per-token stats + 7 conv dots, reduce across the 8 x-lanes
    #pragma unroll
    for (int i = 0; i < 4; i++) {
        float v[8];
        float ph = 0.f, ph2 = 0.f;
        #pragma unroll
        for (int np = 0; np < 4; np++) {
            ull a = acc[i][np];
            float lo = __uint_as_float((unsigned)a);
            float hi = __uint_as_float((unsigned)(a >> 32));
            lo += b1_s[n0 + 2 * np];
            hi += b1_s[n0 + 2 * np + 1];
            lo = 0.5f * lo * (1.f + erff(lo * 0.70710678118f));   // exact GELU
            hi = 0.5f * hi * (1.f + erff(hi * 0.70710678118f));
            v[2 * np]     = lo;
            v[2 * np + 1] = hi;
            ph += lo + hi;
            ph2 += lo * lo + hi * hi;
        }
        ph  += __shfl_xor_sync(0xffffffff, ph, 1);
        ph  += __shfl_xor_sync(0xffffffff, ph, 2);
        ph  += __shfl_xor_sync(0xffffffff, ph, 4);
        ph2 += __shfl_xor_sync(0xffffffff, ph2, 1);
        ph2 += __shfl_xor_sync(0xffffffff, ph2, 2);
        ph2 += __shfl_xor_sync(0xffffffff, ph2, 4);

        float pd[7];
        #pragma unroll
        for (int j = 0; j < 7; j++) {
            float4 ga = *(const float4*)&gw_s[j * 64 + n0];
            float4 gb = *(const float4*)&gw_s[j * 64 + n0 + 4];
            float sum = v[0] * ga.x + v[1] * ga.y + v[2] * ga.z + v[3] * ga.w
                      + v[4] * gb.x + v[5] * gb.y + v[6] * gb.z + v[7] * gb.w;
            sum += __shfl_xor_sync(0xffffffff, sum, 1);
            sum += __shfl_xor_sync(0xffffffff, sum, 2);
            sum += __shfl_xor_sync(0xffffffff, sum, 4);
            pd[j] = sum;
        }
        if (x == 0) {
            float mu   = ph  * (1.f / 64.f);
            float var  = ph2 * (1.f / 64.f) - mu * mu;
            float rstd = rsqrtf(var + 1e-5f);
            int t = t0 + m0 + i;
            #pragma unroll
            for (int j = 0; j < 7; j++)
                g_c[j * (B_ * T_) + b * T_ + t] = (pd[j] - mu * sG[j]) * rstd + sS[j];
        }
    }
}

// ---------------------------------------------------------------------------
// k3: fused conv-shift + ssf + gated tanh + softmax + EXACT top-K
//     radix select with parallel suffix-scan digit pick
// ---------------------------------------------------------------------------
__global__ __launch_bounds__(256) void k3_score_topk(
    const float* __restrict__ ssf_x,
    const float* __restrict__ conv_b, const float* __restrict__ ssf_w,
    const float* __restrict__ ssf_b,  const float* __restrict__ gate,
    float* __restrict__ attn_out)
{
    __shared__ unsigned su[T_];
    __shared__ float redf[256];
    __shared__ unsigned hist[256];
    __shared__ unsigned sfx[256];
    __shared__ unsigned wsum[8];
    __shared__ unsigned s_prefix, s_rem;

    const int b = blockIdx.x, tid = threadIdx.x;
    const float alpha = 1.f / (1.f + expf(-gate[0]));
    const float cb = conv_b[0], sb = ssf_b[0];
    float sw[7];
    #pragma unroll
    for (int i = 0; i < 7; i++) sw[i] = ssf_w[i];

    float av[16];
    float lmax = -CUDART_INF_F;
    #pragma unroll
    for (int i = 0; i < 16; i++) {
        int t = tid + (i << 8);
        float wc = cb;
        #pragma unroll
        for (int j = 0; j < 7; j++) {
            int tt = t + j - 3;
            if ((unsigned)tt < (unsigned)T_)
                wc += g_c[j * (B_ * T_) + b * T_ + tt];
        }
        float ws = sb;
        const float* sx = ssf_x + ((size_t)(b * T_ + t)) * 7;
        #pragma unroll
        for (int p = 0; p < 7; p++) ws += sx[p] * sw[p];
        av[i] = tanhf(alpha * wc + (1.f - alpha) * ws);
        lmax = fmaxf(lmax, av[i]);
    }
    redf[tid] = lmax; __syncthreads();
    for (int st = 128; st > 0; st >>= 1) {
        if (tid < st) redf[tid] = fmaxf(redf[tid], redf[tid + st]);
        __syncthreads();
    }
    float m = redf[0]; __syncthreads();

    float lsum = 0.f;
    #pragma unroll
    for (int i = 0; i < 16; i++) { av[i] = expf(av[i] - m); lsum += av[i]; }
    redf[tid] = lsum; __syncthreads();
    for (int st = 128; st > 0; st >>= 1) {
        if (tid < st) redf[tid] += redf[tid + st];
        __syncthreads();
    }
    float invZ = 1.f / redf[0];

    #pragma unroll
    for (int i = 0; i < 16; i++) {
        int t = tid + (i << 8);
        float p = av[i] * invZ;
        if (attn_out) attn_out[b * T_ + t] = p;
        su[t] = __float_as_uint(p) + 1u;
    }
    __syncthreads();

    unsigned prefix = 0, remaining = K_;
    for (int shift = 24; shift >= 0; shift -= 8) {
        hist[tid] = 0; __syncthreads();
        #pragma unroll
        for (int i = 0; i < 16; i++) {
            unsigned uu = su[tid + (i << 8)];
            bool cand = (shift == 24) ? true : (((uu ^ prefix) >> (shift + 8)) == 0);
            if (cand) atomicAdd(&hist[(uu >> shift) & 255], 1u);
        }
        __syncthreads();
        // parallel inclusive suffix-sum of hist
        sfx[tid] = hist[tid]; __syncthreads();
        #pragma unroll
        for (int off = 1; off < 256; off <<= 1) {
            unsigned vv = (tid + off < 256) ? sfx[tid + off] : 0u;
            __syncthreads();
            sfx[tid] += vv;
            __syncthreads();
        }
        unsigned s_d  = sfx[tid];
        unsigned s_d1 = (tid < 255) ? sfx[tid + 1] : 0u;
        if (s_d >= remaining && s_d1 < remaining) {
            s_prefix = prefix | ((unsigned)tid << shift);
            s_rem    = remaining - s_d1;
        }
        __syncthreads();
        prefix = s_prefix; remaining = s_rem;
        __syncthreads();
    }
    const unsigned ustar = prefix;
    const unsigned r = remaining;

    const int base = tid << 4;
    unsigned gt = 0, eq = 0;
    #pragma unroll
    for (int i = 0; i < 16; i++) {
        unsigned uu = su[base + i];
        gt += (uu > ustar); eq += (uu == ustar);
    }
    unsigned pk = (gt << 16) | eq;
    const int lane = tid & 31, wd = tid >> 5;
    unsigned inc = pk;
    #pragma unroll
    for (int off = 1; off < 32; off <<= 1) {
        unsigned vv = __shfl_up_sync(0xffffffffu, inc, off);
        if (lane >= off) inc += vv;
    }
    if (lane == 31) wsum[wd] = inc;
    __syncthreads();
    if (tid < 8) {
        unsigned vv = wsum[tid], s2 = vv;
        #pragma unroll
        for (int off = 1; off < 8; off <<= 1) {
            unsigned w2 = __shfl_up_sync(0xffu, s2, off);
            if (tid >= off) s2 += w2;
        }
        wsum[tid] = s2 - vv;
    }
    __syncthreads();
    unsigned ex = inc - pk + wsum[wd];
    unsigned gt_run = ex >> 16, eq_run = ex & 0xffff;
    #pragma unroll
    for (int i = 0; i < 16; i++) {
        int t = base + i;
        unsigned uu = su[t];
        if (uu > ustar) {
            g_idx[b * K_ + gt_run + min(eq_run, r)] = t;
            gt_run++;
        } else if (uu == ustar) {
            if (eq_run < r) g_idx[b * K_ + gt_run + eq_run] = t;
            eq_run++;
        }
    }
}

// ---------------------------------------------------------------------------
// k4: gather pooled rows (float4), 2 rows per 256-thread block
// ---------------------------------------------------------------------------
__global__ __launch_bounds__(256) void k4_gather(
    const float* __restrict__ emb, float* __restrict__ pooled)
{
    int bk = blockIdx.x * 2 + (threadIdx.x >> 7);
    int l  = threadIdx.x & 127;
    int b  = bk >> 9;
    int t  = g_idx[bk];
    const float4* src = (const float4*)(emb + (size_t)(b * T_ + t) * E_);
    float4* dst = (float4*)(pooled + (size_t)bk * E_);
    dst[l] = src[l];
}

// ---------------------------------------------------------------------------
extern "C" void kernel_launch(void* const* d_in, const int* in_sizes, int n_in,
                              void* d_out, int out_size)
{
    // handle possible dropped bool padding_mask (slots shift by one)
    int s = (in_sizes[2] == E_ * R_) ? -1 : 0;

    const float* emb   = (const float*)d_in[0];
    const float* ssfx  = (const float*)d_in[1];
    const float* W1    = (const float*)d_in[3 + s];
    const float* b1    = (const float*)d_in[4 + s];
    const float* ln_g  = (const float*)d_in[5 + s];
    const float* ln_b  = (const float*)d_in[6 + s];
    const float* convw = (const float*)d_in[7 + s];
    const float* convb = (const float*)d_in[8 + s];
    const float* ssfw  = (const float*)d_in[9 + s];
    const float* ssfb  = (const float*)d_in[10 + s];
    const float* gate  = (const float*)d_in[11 + s];

    const long long PO = (long long)B_ * K_ * E_;
    const long long AT = (long long)B_ * T_;

    float* pooled = (float*)d_out;
    float* attn = (out_size >= PO + AT) ? ((float*)d_out + PO) : nullptr;

    k1_gemm<<<(B_ * T_) / 128, 256>>>(emb, W1, b1, ln_g, ln_b, convw);
    k3_score_topk<<<B_, 256>>>(ssfx, convb, ssfw, ssfb, gate, attn);
    k4_gather<<<(B_ * K_) / 2, 256>>>(emb, pooled);
}

// round 10
// speedup vs baseline: 1.9079x; 1.9079x over previous
#include <cuda_runtime.h>
#include <cuda_bf16.h>
#include <cstdint>
#include <math_constants.h>

#define B_ 32
#define T_ 4096
#define E_ 512
#define R_ 64
#define K_ 512

// scratch (no allocations allowed)
__device__ float g_c[7 * B_ * T_];            // c_j[b,t] per conv tap
__device__ int   g_idx[B_ * K_];              // ascending selected indices
__device__ __nv_bfloat16 g_Wh[R_ * E_];       // W^T hi  [n][k]
__device__ __nv_bfloat16 g_Wl[R_ * E_];       // W^T lo

__device__ __forceinline__ uint32_t smem_u32(const void* p) {
    uint32_t a;
    asm("{ .reg .u64 t; cvta.to.shared.u64 t, %1; cvt.u32.u64 %0, t; }"
        : "=r"(a) : "l"(p));
    return a;
}
__device__ __forceinline__ void split2(float a, unsigned short& h, unsigned short& l) {
    __nv_bfloat16 bh = __float2bfloat16_rn(a);
    float r1 = a - __bfloat162float(bh);
    __nv_bfloat16 bl = __float2bfloat16_rn(r1);
    h = *(unsigned short*)&bh; l = *(unsigned short*)&bl;
}
__device__ __forceinline__ uint32_t bpack(unsigned short a, unsigned short b) {
    return (uint32_t)a | ((uint32_t)b << 16);
}
__device__ __forceinline__ void ldm4(uint32_t& r0, uint32_t& r1, uint32_t& r2,
                                     uint32_t& r3, uint32_t addr) {
    asm volatile("ldmatrix.sync.aligned.m8n8.x4.shared.b16 {%0,%1,%2,%3}, [%4];"
                 : "=r"(r0), "=r"(r1), "=r"(r2), "=r"(r3) : "r"(addr));
}
__device__ __forceinline__ void mma16816(float* d, const uint32_t* a,
                                         uint32_t b0, uint32_t b1) {
    asm volatile("mma.sync.aligned.m16n8k16.row.col.f32.bf16.bf16.f32 "
                 "{%0,%1,%2,%3}, {%4,%5,%6,%7}, {%8,%9}, {%0,%1,%2,%3};"
                 : "+f"(d[0]), "+f"(d[1]), "+f"(d[2]), "+f"(d[3])
                 : "r"(a[0]), "r"(a[1]), "r"(a[2]), "r"(a[3]), "r"(b0), "r"(b1));
}

// ---------------------------------------------------------------------------
// k0: transpose + 2-way split W1 [512,64] -> Wt[64,512] bf16 hi/lo
// ---------------------------------------------------------------------------
__global__ __launch_bounds__(256) void k0_prep(const float* __restrict__ W1) {
    int i = blockIdx.x * 256 + threadIdx.x;       // i = n*512 + k
    int n = i >> 9, k = i & 511;
    float w = W1[k * 64 + n];
    unsigned short h, l;
    split2(w, h, l);
    g_Wh[i] = *(__nv_bfloat16*)&h;
    g_Wl[i] = *(__nv_bfloat16*)&l;
}

// ---------------------------------------------------------------------------
// k1: HMMA GEMM (128m x 64n per CTA, k chunks of 16) with 2-way bf16 split
//     (3 products: hh,hl,lh; ll term < 2^-18 -> exactness preserved),
//     fused bias + exact GELU + folded LayerNorm+conv epilogue
// ---------------------------------------------------------------------------
#define AST 24     // bf16 stride per A row (48B: conflict-free, 16B aligned)
#define BST 24
__global__ __launch_bounds__(256, 2) void k1_mma(
    const float* __restrict__ emb, const float* __restrict__ b1,
    const float* __restrict__ ln_g, const float* __restrict__ ln_b,
    const float* __restrict__ conv_w)
{
    __shared__ __align__(16) unsigned short As[2][2][128 * AST];  // 24576 B
    __shared__ __align__(16) unsigned short Bs[2][64 * BST];      //  6144 B
    __shared__ float gw_s[7 * 64];
    __shared__ float b1_s[64];
    __shared__ float sG[7], sS[7];

    const int tid  = threadIdx.x;
    const int w    = tid >> 5;
    const int lane = tid & 31;
    const int b    = blockIdx.x >> 5;
    const int t0   = (blockIdx.x & 31) << 7;

    for (int i = tid; i < 448; i += 256) gw_s[i] = ln_g[i & 63] * conv_w[i];
    if (tid < 64) b1_s[tid] = b1[tid];
    __syncthreads();
    if (tid < 7) {
        float G = 0.f, S = 0.f;
        #pragma unroll 8
        for (int r = 0; r < 64; r++) {
            G += gw_s[tid * 64 + r];
            S += ln_b[r] * conv_w[tid * 64 + r];
        }
        sG[tid] = G; sS[tid] = S;
    }

    const float* embB = emb + (size_t)(b * T_ + t0) * E_;

    // staging coords
    const int arow = tid >> 1;               // 0..127
    const int ak8  = (tid & 1) << 3;         // 0 or 8
    const int bn   = tid >> 2;               // 0..63
    const int bk4  = (tid & 3) << 2;         // 0,4,8,12

    // ldmatrix lane-invariant offsets (bytes)
    const uint32_t a_off = (uint32_t)(((16 * w + (lane & 15)) * AST + (lane >> 4) * 8) * 2);
    const int g = lane >> 3;
    const uint32_t b_off = (uint32_t)((((g >> 1) * 8 + (lane & 7)) * BST + (g & 1) * 8) * 2);

    uint32_t As_base[2][2], Bs_base[2];
    #pragma unroll
    for (int bf = 0; bf < 2; bf++)
        #pragma unroll
        for (int s = 0; s < 2; s++) As_base[bf][s] = smem_u32(As[bf][s]);
    #pragma unroll
    for (int s = 0; s < 2; s++) Bs_base[s] = smem_u32(Bs[s]);

    float acc[8][4];
    #pragma unroll
    for (int i = 0; i < 8; i++)
        #pragma unroll
        for (int j = 0; j < 4; j++) acc[i][j] = 0.f;

    // prefetch chunk 0
    float4 pa0 = *(const float4*)&embB[(size_t)arow * E_ + ak8];
    float4 pa1 = *(const float4*)&embB[(size_t)arow * E_ + ak8 + 4];
    uint2 pb0 = *(const uint2*)&g_Wh[(size_t)bn * E_ + bk4];
    uint2 pb1 = *(const uint2*)&g_Wl[(size_t)bn * E_ + bk4];

    for (int c = 0; c < 32; c++) {
        const int buf = c & 1;
        // --- A convert + store (buf safe: last read was mma(c-2)) ---
        {
            float f[8] = {pa0.x, pa0.y, pa0.z, pa0.w, pa1.x, pa1.y, pa1.z, pa1.w};
            unsigned short h[8], l[8];
            #pragma unroll
            for (int i = 0; i < 8; i++) split2(f[i], h[i], l[i]);
            uint32_t o = arow * AST + ak8;
            *(uint4*)&As[buf][0][o] = make_uint4(bpack(h[0], h[1]), bpack(h[2], h[3]),
                                                 bpack(h[4], h[5]), bpack(h[6], h[7]));
            *(uint4*)&As[buf][1][o] = make_uint4(bpack(l[0], l[1]), bpack(l[2], l[3]),
                                                 bpack(l[4], l[5]), bpack(l[6], l[7]));
        }
        __syncthreads();                    // S1: mma(c-1) complete -> B writable
        {
            uint32_t o = bn * BST + bk4;
            *(uint2*)&Bs[0][o] = pb0;
            *(uint2*)&Bs[1][o] = pb1;
        }
        if (c + 1 < 32) {                   // prefetch next chunk (hidden by mma)
            int kc = (c + 1) << 4;
            pa0 = *(const float4*)&embB[(size_t)arow * E_ + kc + ak8];
            pa1 = *(const float4*)&embB[(size_t)arow * E_ + kc + ak8 + 4];
            pb0 = *(const uint2*)&g_Wh[(size_t)bn * E_ + kc + bk4];
            pb1 = *(const uint2*)&g_Wl[(size_t)bn * E_ + kc + bk4];
        }
        __syncthreads();                    // S2: stores visible

        // --- A fragments (2 splits) ---
        uint32_t af[2][4];
        #pragma unroll
        for (int s = 0; s < 2; s++)
            ldm4(af[s][0], af[s][1], af[s][2], af[s][3], As_base[buf][s] + a_off);

        // --- per n-tile-pair: B frags + 3-product MMA ---
        #pragma unroll
        for (int p = 0; p < 4; p++) {
            uint32_t bh[4], bl[4];
            uint32_t po = (uint32_t)(p * 16 * BST * 2);
            ldm4(bh[0], bh[1], bh[2], bh[3], Bs_base[0] + b_off + po);
            ldm4(bl[0], bl[1], bl[2], bl[3], Bs_base[1] + b_off + po);
            #pragma unroll
            for (int half = 0; half < 2; half++) {
                int nt = 2 * p + half;
                uint32_t h0 = bh[2 * half], h1 = bh[2 * half + 1];
                uint32_t l0 = bl[2 * half], l1 = bl[2 * half + 1];
                mma16816(acc[nt], af[0], h0, h1);   // hh
                mma16816(acc[nt], af[0], l0, l1);   // hl
                mma16816(acc[nt], af[1], h0, h1);   // lh
            }
        }
    }

    // ------------------ epilogue: GELU + LN + conv fold -------------------
    // fragment: thread holds rows r0 = 16w + lane/4 and r1 = r0+8;
    // cols: nt*8 + (lane&3)*2 + {0,1}
    const int q = lane & 3;
    #pragma unroll
    for (int rr = 0; rr < 2; rr++) {
        float ph = 0.f, ph2 = 0.f;
        float v[16];
        #pragma unroll
        for (int nt = 0; nt < 8; nt++) {
            #pragma unroll
            for (int e = 0; e < 2; e++) {
                int col = nt * 8 + q * 2 + e;
                float x = acc[nt][rr * 2 + e] + b1_s[col];
                x = 0.5f * x * (1.f + erff(x * 0.70710678118f));   // exact GELU
                v[nt * 2 + e] = x;
                ph += x; ph2 += x * x;
            }
        }
        ph  += __shfl_xor_sync(0xffffffff, ph, 1);
        ph  += __shfl_xor_sync(0xffffffff, ph, 2);
        ph2 += __shfl_xor_sync(0xffffffff, ph2, 1);
        ph2 += __shfl_xor_sync(0xffffffff, ph2, 2);

        float pd[7];
        #pragma unroll
        for (int j = 0; j < 7; j++) {
            float sum = 0.f;
            #pragma unroll
            for (int nt = 0; nt < 8; nt++) {
                int col = nt * 8 + q * 2;
                sum += v[nt * 2] * gw_s[j * 64 + col]
                     + v[nt * 2 + 1] * gw_s[j * 64 + col + 1];
            }
            sum += __shfl_xor_sync(0xffffffff, sum, 1);
            sum += __shfl_xor_sync(0xffffffff, sum, 2);
            pd[j] = sum;
        }
        if (q == 0) {
            float mu   = ph  * (1.f / 64.f);
            float var  = ph2 * (1.f / 64.f) - mu * mu;
            float rstd = rsqrtf(var + 1e-5f);
            int t = t0 + 16 * w + (lane >> 2) + rr * 8;
            #pragma unroll
            for (int j = 0; j < 7; j++)
                g_c[j * (B_ * T_) + b * T_ + t] = (pd[j] - mu * sG[j]) * rstd + sS[j];
        }
    }
}

// ---------------------------------------------------------------------------
// k3: fused conv-shift + ssf + gated tanh + softmax + EXACT top-K
//     radix select with parallel suffix-scan digit pick
// ---------------------------------------------------------------------------
__global__ __launch_bounds__(256) void k3_score_topk(
    const float* __restrict__ ssf_x,
    const float* __restrict__ conv_b, const float* __restrict__ ssf_w,
    const float* __restrict__ ssf_b,  const float* __restrict__ gate,
    float* __restrict__ attn_out)
{
    __shared__ unsigned su[T_];
    __shared__ float redf[256];
    __shared__ unsigned hist[256];
    __shared__ unsigned sfx[256];
    __shared__ unsigned wsum[8];
    __shared__ unsigned s_prefix, s_rem;

    const int b = blockIdx.x, tid = threadIdx.x;
    const float alpha = 1.f / (1.f + expf(-gate[0]));
    const float cb = conv_b[0], sb = ssf_b[0];
    float sw[7];
    #pragma unroll
    for (int i = 0; i < 7; i++) sw[i] = ssf_w[i];

    float av[16];
    float lmax = -CUDART_INF_F;
    #pragma unroll
    for (int i = 0; i < 16; i++) {
        int t = tid + (i << 8);
        float wc = cb;
        #pragma unroll
        for (int j = 0; j < 7; j++) {
            int tt = t + j - 3;
            if ((unsigned)tt < (unsigned)T_)
                wc += g_c[j * (B_ * T_) + b * T_ + tt];
        }
        float ws = sb;
        const float* sx = ssf_x + ((size_t)(b * T_ + t)) * 7;
        #pragma unroll
        for (int p = 0; p < 7; p++) ws += sx[p] * sw[p];
        av[i] = tanhf(alpha * wc + (1.f - alpha) * ws);
        lmax = fmaxf(lmax, av[i]);
    }
    redf[tid] = lmax; __syncthreads();
    for (int st = 128; st > 0; st >>= 1) {
        if (tid < st) redf[tid] = fmaxf(redf[tid], redf[tid + st]);
        __syncthreads();
    }
    float m = redf[0]; __syncthreads();

    float lsum = 0.f;
    #pragma unroll
    for (int i = 0; i < 16; i++) { av[i] = expf(av[i] - m); lsum += av[i]; }
    redf[tid] = lsum; __syncthreads();
    for (int st = 128; st > 0; st >>= 1) {
        if (tid < st) redf[tid] += redf[tid + st];
        __syncthreads();
    }
    float invZ = 1.f / redf[0];

    #pragma unroll
    for (int i = 0; i < 16; i++) {
        int t = tid + (i << 8);
        float p = av[i] * invZ;
        if (attn_out) attn_out[b * T_ + t] = p;
        su[t] = __float_as_uint(p) + 1u;
    }
    __syncthreads();

    unsigned prefix = 0, remaining = K_;
    for (int shift = 24; shift >= 0; shift -= 8) {
        hist[tid] = 0; __syncthreads();
        #pragma unroll
        for (int i = 0; i < 16; i++) {
            unsigned uu = su[tid + (i << 8)];
            bool cand = (shift == 24) ? true : (((uu ^ prefix) >> (shift + 8)) == 0);
            if (cand) atomicAdd(&hist[(uu >> shift) & 255], 1u);
        }
        __syncthreads();
        // parallel inclusive suffix-sum of hist
        sfx[tid] = hist[tid]; __syncthreads();
        #pragma unroll
        for (int off = 1; off < 256; off <<= 1) {
            unsigned vv = (tid + off < 256) ? sfx[tid + off] : 0u;
            __syncthreads();
            sfx[tid] += vv;
            __syncthreads();
        }
        unsigned s_d  = sfx[tid];
        unsigned s_d1 = (tid < 255) ? sfx[tid + 1] : 0u;
        if (s_d >= remaining && s_d1 < remaining) {
            s_prefix = prefix | ((unsigned)tid << shift);
            s_rem    = remaining - s_d1;
        }
        __syncthreads();
        prefix = s_prefix; remaining = s_rem;
        __syncthreads();
    }
    const unsigned ustar = prefix;
    const unsigned r = remaining;

    const int base = tid << 4;
    unsigned gt = 0, eq = 0;
    #pragma unroll
    for (int i = 0; i < 16; i++) {
        unsigned uu = su[base + i];
        gt += (uu > ustar); eq += (uu == ustar);
    }
    unsigned pk = (gt << 16) | eq;
    const int lane = tid & 31, wd = tid >> 5;
    unsigned inc = pk;
    #pragma unroll
    for (int off = 1; off < 32; off <<= 1) {
        unsigned vv = __shfl_up_sync(0xffffffffu, inc, off);
        if (lane >= off) inc += vv;
    }
    if (lane == 31) wsum[wd] = inc;
    __syncthreads();
    if (tid < 8) {
        unsigned vv = wsum[tid], s2 = vv;
        #pragma unroll
        for (int off = 1; off < 8; off <<= 1) {
            unsigned w2 = __shfl_up_sync(0xffu, s2, off);
            if (tid >= off) s2 += w2;
        }
        wsum[tid] = s2 - vv;
    }
    __syncthreads();
    unsigned ex = inc - pk + wsum[wd];
    unsigned gt_run = ex >> 16, eq_run = ex & 0xffff;
    #pragma unroll
    for (int i = 0; i < 16; i++) {
        int t = base + i;
        unsigned uu = su[t];
        if (uu > ustar) {
            g_idx[b * K_ + gt_run + min(eq_run, r)] = t;
            gt_run++;
        } else if (uu == ustar) {
            if (eq_run < r) g_idx[b * K_ + gt_run + eq_run] = t;
            eq_run++;
        }
    }
}

// ---------------------------------------------------------------------------
// k4: gather pooled rows (float4), 2 rows per 256-thread block
// ---------------------------------------------------------------------------
__global__ __launch_bounds__(256) void k4_gather(
    const float* __restrict__ emb, float* __restrict__ pooled)
{
    int bk = blockIdx.x * 2 + (threadIdx.x >> 7);
    int l  = threadIdx.x & 127;
    int b  = bk >> 9;
    int t  = g_idx[bk];
    const float4* src = (const float4*)(emb + (size_t)(b * T_ + t) * E_);
    float4* dst = (float4*)(pooled + (size_t)bk * E_);
    dst[l] = src[l];
}

// ---------------------------------------------------------------------------
extern "C" void kernel_launch(void* const* d_in, const int* in_sizes, int n_in,
                              void* d_out, int out_size)
{
    // handle possible dropped bool padding_mask (slots shift by one)
    int s = (in_sizes[2] == E_ * R_) ? -1 : 0;

    const float* emb   = (const float*)d_in[0];
    const float* ssfx  = (const float*)d_in[1];
    const float* W1    = (const float*)d_in[3 + s];
    const float* b1    = (const float*)d_in[4 + s];
    const float* ln_g  = (const float*)d_in[5 + s];
    const float* ln_b  = (const float*)d_in[6 + s];
    const float* convw = (const float*)d_in[7 + s];
    const float* convb = (const float*)d_in[8 + s];
    const float* ssfw  = (const float*)d_in[9 + s];
    const float* ssfb  = (const float*)d_in[10 + s];
    const float* gate  = (const float*)d_in[11 + s];

    const long long PO = (long long)B_ * K_ * E_;
    const long long AT = (long long)B_ * T_;

    float* pooled = (float*)d_out;
    float* attn = (out_size >= PO + AT) ? ((float*)d_out + PO) : nullptr;

    k0_prep<<<(R_ * E_) / 256, 256>>>(W1);
    k1_mma<<<(B_ * T_) / 128, 256>>>(emb, b1, ln_g, ln_b, convw);
    k3_score_topk<<<B_, 256>>>(ssfx, convb, ssfw, ssfb, gate, attn);
    k4_gather<<<(B_ * K_) / 2, 256>>>(emb, pooled);
}

// round 11
// speedup vs baseline: 2.2222x; 1.1648x over previous
#include <cuda_runtime.h>
#include <cuda_bf16.h>
#include <cstdint>
#include <math_constants.h>

#define B_ 32
#define T_ 4096
#define E_ 512
#define R_ 64
#define K_ 512

// scratch (no allocations allowed)
__device__ float g_c[7 * B_ * T_];     // c_j[b,t] per conv tap
__device__ int   g_idx[B_ * K_];       // ascending selected indices
__device__ uint4 g_Bf[32 * 4 * 2 * 32]; // B frags [chunk][p][split][lane] (128 KB)

__device__ __forceinline__ void split2(float a, unsigned short& h, unsigned short& l) {
    __nv_bfloat16 bh = __float2bfloat16_rn(a);
    float r1 = a - __bfloat162float(bh);
    __nv_bfloat16 bl = __float2bfloat16_rn(r1);
    h = *(unsigned short*)&bh; l = *(unsigned short*)&bl;
}
__device__ __forceinline__ uint32_t bpack(unsigned short a, unsigned short b) {
    return (uint32_t)a | ((uint32_t)b << 16);
}
__device__ __forceinline__ void mma16816(float* d, const uint32_t* a,
                                         uint32_t b0, uint32_t b1) {
    asm volatile("mma.sync.aligned.m16n8k16.row.col.f32.bf16.bf16.f32 "
                 "{%0,%1,%2,%3}, {%4,%5,%6,%7}, {%8,%9}, {%0,%1,%2,%3};"
                 : "+f"(d[0]), "+f"(d[1]), "+f"(d[2]), "+f"(d[3])
                 : "r"(a[0]), "r"(a[1]), "r"(a[2]), "r"(a[3]), "r"(b0), "r"(b1));
}

// ---------------------------------------------------------------------------
// k0: build B fragments in mma.sync register order, 2-way bf16 split.
// mma m16n8k16 B frag: reg0 = B[k=(l&3)*2 + {0,1}][n=l>>2], reg1 = same k+8.
// uint4 per (c,p,s,lane): {half0.reg0, half0.reg1, half1.reg0, half1.reg1},
// n = p*16 + half*8 + (l>>2), k = c*16 + (l&3)*2 (+8 for reg1).
// ---------------------------------------------------------------------------
__global__ __launch_bounds__(256) void k0_prep(const float* __restrict__ W1) {
    int idx  = blockIdx.x * 256 + threadIdx.x;   // 0..8191
    int lane = idx & 31;
    int s    = (idx >> 5) & 1;
    int p    = (idx >> 6) & 3;
    int c    = idx >> 8;
    uint32_t wv[4];
    #pragma unroll
    for (int w = 0; w < 4; w++) {
        int half = w >> 1, r = w & 1;
        int n  = p * 16 + half * 8 + (lane >> 2);
        int k0 = c * 16 + (lane & 3) * 2 + r * 8;
        unsigned short h0, l0, h1, l1;
        split2(W1[k0 * 64 + n], h0, l0);
        split2(W1[(k0 + 1) * 64 + n], h1, l1);
        wv[w] = (s == 0) ? bpack(h0, h1) : bpack(l0, l1);
    }
    g_Bf[idx] = make_uint4(wv[0], wv[1], wv[2], wv[3]);
}

// ---------------------------------------------------------------------------
// k1: HMMA GEMM, NO shared-memory staging, NO loop barriers.
// 128m x 64n per CTA; warp owns 16 m-rows; A frags built from direct LDG+
// split2; B frags fetched pre-packed from g_Bf (L2-hot, coalesced).
// 3 products (hh, hl, lh) per k-chunk of 16; fp32 accum.
// ---------------------------------------------------------------------------
__global__ __launch_bounds__(256, 2) void k1_mma(
    const float* __restrict__ emb, const float* __restrict__ b1,
    const float* __restrict__ ln_g, const float* __restrict__ ln_b,
    const float* __restrict__ conv_w)
{
    __shared__ float gw_s[7 * 64];
    __shared__ float b1_s[64];
    __shared__ float sG[7], sS[7];

    const int tid  = threadIdx.x;
    const int w    = tid >> 5;
    const int lane = tid & 31;
    const int q    = lane & 3;
    const int b    = blockIdx.x >> 5;
    const int t0   = (blockIdx.x & 31) << 7;

    for (int i = tid; i < 448; i += 256) gw_s[i] = ln_g[i & 63] * conv_w[i];
    if (tid < 64) b1_s[tid] = b1[tid];
    __syncthreads();
    if (tid < 7) {
        float G = 0.f, S = 0.f;
        #pragma unroll 8
        for (int r = 0; r < 64; r++) {
            G += gw_s[tid * 64 + r];
            S += ln_b[r] * conv_w[tid * 64 + r];
        }
        sG[tid] = G; sS[tid] = S;
    }

    // this thread's two A rows
    const int r0g = t0 + 16 * w + (lane >> 2);
    const float* pa0 = emb + (size_t)(b * T_ + r0g) * E_;
    const float* pa1 = pa0 + 8 * E_;

    float acc[8][4];
    #pragma unroll
    for (int i = 0; i < 8; i++)
        #pragma unroll
        for (int j = 0; j < 4; j++) acc[i][j] = 0.f;

    for (int c = 0; c < 32; c++) {
        const int k0 = (c << 4) + (q << 1);

        // B fragments: 8 coalesced LDG.128 from L2-hot pre-packed array
        uint4 Bv[8];
        #pragma unroll
        for (int p = 0; p < 4; p++) {
            #pragma unroll
            for (int s = 0; s < 2; s++)
                Bv[p * 2 + s] = g_Bf[((((c << 2) + p) << 1) + s) * 32 + lane];
        }

        // A: 4 direct LDG.64 (rows r0, r1; k pairs k0 and k0+8)
        float2 a00 = *(const float2*)&pa0[k0];
        float2 a10 = *(const float2*)&pa1[k0];
        float2 a01 = *(const float2*)&pa0[k0 + 8];
        float2 a11 = *(const float2*)&pa1[k0 + 8];

        // convert to 2-way split frags (a0,a1,a2,a3 order of mma A frag)
        unsigned short h0a, l0a, h0b, l0b, h1a, l1a, h1b, l1b;
        unsigned short h2a, l2a, h2b, l2b, h3a, l3a, h3b, l3b;
        split2(a00.x, h0a, l0a); split2(a00.y, h0b, l0b);
        split2(a10.x, h1a, l1a); split2(a10.y, h1b, l1b);
        split2(a01.x, h2a, l2a); split2(a01.y, h2b, l2b);
        split2(a11.x, h3a, l3a); split2(a11.y, h3b, l3b);
        uint32_t afh[4] = {bpack(h0a, h0b), bpack(h1a, h1b),
                           bpack(h2a, h2b), bpack(h3a, h3b)};
        uint32_t afl[4] = {bpack(l0a, l0b), bpack(l1a, l1b),
                           bpack(l2a, l2b), bpack(l3a, l3b)};

        // 3-product MMA per n-tile
        #pragma unroll
        for (int p = 0; p < 4; p++) {
            uint4 bh4 = Bv[p * 2 + 0];
            uint4 bl4 = Bv[p * 2 + 1];
            #pragma unroll
            for (int half = 0; half < 2; half++) {
                int nt = p * 2 + half;
                uint32_t b0 = half ? bh4.z : bh4.x;
                uint32_t b1v = half ? bh4.w : bh4.y;
                uint32_t l0 = half ? bl4.z : bl4.x;
                uint32_t l1v = half ? bl4.w : bl4.y;
                mma16816(acc[nt], afh, b0, b1v);   // hh
                mma16816(acc[nt], afh, l0, l1v);   // hl
                mma16816(acc[nt], afl, b0, b1v);   // lh
            }
        }
    }

    // ------------------ epilogue: GELU + LN + conv fold -------------------
    #pragma unroll
    for (int rr = 0; rr < 2; rr++) {
        float ph = 0.f, ph2 = 0.f;
        float v[16];
        #pragma unroll
        for (int nt = 0; nt < 8; nt++) {
            #pragma unroll
            for (int e = 0; e < 2; e++) {
                int col = nt * 8 + q * 2 + e;
                float x = acc[nt][rr * 2 + e] + b1_s[col];
                x = 0.5f * x * (1.f + erff(x * 0.70710678118f));   // exact GELU
                v[nt * 2 + e] = x;
                ph += x; ph2 += x * x;
            }
        }
        ph  += __shfl_xor_sync(0xffffffff, ph, 1);
        ph  += __shfl_xor_sync(0xffffffff, ph, 2);
        ph2 += __shfl_xor_sync(0xffffffff, ph2, 1);
        ph2 += __shfl_xor_sync(0xffffffff, ph2, 2);

        float pd[7];
        #pragma unroll
        for (int j = 0; j < 7; j++) {
            float sum = 0.f;
            #pragma unroll
            for (int nt = 0; nt < 8; nt++) {
                int col = nt * 8 + q * 2;
                sum += v[nt * 2] * gw_s[j * 64 + col]
                     + v[nt * 2 + 1] * gw_s[j * 64 + col + 1];
            }
            sum += __shfl_xor_sync(0xffffffff, sum, 1);
            sum += __shfl_xor_sync(0xffffffff, sum, 2);
            pd[j] = sum;
        }
        if (q == 0) {
            float mu   = ph  * (1.f / 64.f);
            float var  = ph2 * (1.f / 64.f) - mu * mu;
            float rstd = rsqrtf(var + 1e-5f);
            int t = t0 + 16 * w + (lane >> 2) + rr * 8;
            #pragma unroll
            for (int j = 0; j < 7; j++)
                g_c[j * (B_ * T_) + b * T_ + t] = (pd[j] - mu * sG[j]) * rstd + sS[j];
        }
    }
}

// ---------------------------------------------------------------------------
// k3: fused conv-shift + ssf + gated tanh + softmax + EXACT top-K
//     radix select with parallel suffix-scan digit pick
// ---------------------------------------------------------------------------
__global__ __launch_bounds__(256) void k3_score_topk(
    const float* __restrict__ ssf_x,
    const float* __restrict__ conv_b, const float* __restrict__ ssf_w,
    const float* __restrict__ ssf_b,  const float* __restrict__ gate,
    float* __restrict__ attn_out)
{
    __shared__ unsigned su[T_];
    __shared__ float redf[256];
    __shared__ unsigned hist[256];
    __shared__ unsigned sfx[256];
    __shared__ unsigned wsum[8];
    __shared__ unsigned s_prefix, s_rem;

    const int b = blockIdx.x, tid = threadIdx.x;
    const float alpha = 1.f / (1.f + expf(-gate[0]));
    const float cb = conv_b[0], sb = ssf_b[0];
    float sw[7];
    #pragma unroll
    for (int i = 0; i < 7; i++) sw[i] = ssf_w[i];

    float av[16];
    float lmax = -CUDART_INF_F;
    #pragma unroll
    for (int i = 0; i < 16; i++) {
        int t = tid + (i << 8);
        float wc = cb;
        #pragma unroll
        for (int j = 0; j < 7; j++) {
            int tt = t + j - 3;
            if ((unsigned)tt < (unsigned)T_)
                wc += g_c[j * (B_ * T_) + b * T_ + tt];
        }
        float ws = sb;
        const float* sx = ssf_x + ((size_t)(b * T_ + t)) * 7;
        #pragma unroll
        for (int p = 0; p < 7; p++) ws += sx[p] * sw[p];
        av[i] = tanhf(alpha * wc + (1.f - alpha) * ws);
        lmax = fmaxf(lmax, av[i]);
    }
    redf[tid] = lmax; __syncthreads();
    for (int st = 128; st > 0; st >>= 1) {
        if (tid < st) redf[tid] = fmaxf(redf[tid], redf[tid + st]);
        __syncthreads();
    }
    float m = redf[0]; __syncthreads();

    float lsum = 0.f;
    #pragma unroll
    for (int i = 0; i < 16; i++) { av[i] = expf(av[i] - m); lsum += av[i]; }
    redf[tid] = lsum; __syncthreads();
    for (int st = 128; st > 0; st >>= 1) {
        if (tid < st) redf[tid] += redf[tid + st];
        __syncthreads();
    }
    float invZ = 1.f / redf[0];

    #pragma unroll
    for (int i = 0; i < 16; i++) {
        int t = tid + (i << 8);
        float p = av[i] * invZ;
        if (attn_out) attn_out[b * T_ + t] = p;
        su[t] = __float_as_uint(p) + 1u;
    }
    __syncthreads();

    unsigned prefix = 0, remaining = K_;
    for (int shift = 24; shift >= 0; shift -= 8) {
        hist[tid] = 0; __syncthreads();
        #pragma unroll
        for (int i = 0; i < 16; i++) {
            unsigned uu = su[tid + (i << 8)];
            bool cand = (shift == 24) ? true : (((uu ^ prefix) >> (shift + 8)) == 0);
            if (cand) atomicAdd(&hist[(uu >> shift) & 255], 1u);
        }
        __syncthreads();
        sfx[tid] = hist[tid]; __syncthreads();
        #pragma unroll
        for (int off = 1; off < 256; off <<= 1) {
            unsigned vv = (tid + off < 256) ? sfx[tid + off] : 0u;
            __syncthreads();
            sfx[tid] += vv;
            __syncthreads();
        }
        unsigned s_d  = sfx[tid];
        unsigned s_d1 = (tid < 255) ? sfx[tid + 1] : 0u;
        if (s_d >= remaining && s_d1 < remaining) {
            s_prefix = prefix | ((unsigned)tid << shift);
            s_rem    = remaining - s_d1;
        }
        __syncthreads();
        prefix = s_prefix; remaining = s_rem;
        __syncthreads();
    }
    const unsigned ustar = prefix;
    const unsigned r = remaining;

    const int base = tid << 4;
    unsigned gt = 0, eq = 0;
    #pragma unroll
    for (int i = 0; i < 16; i++) {
        unsigned uu = su[base + i];
        gt += (uu > ustar); eq += (uu == ustar);
    }
    unsigned pk = (gt << 16) | eq;
    const int lane = tid & 31, wd = tid >> 5;
    unsigned inc = pk;
    #pragma unroll
    for (int off = 1; off < 32; off <<= 1) {
        unsigned vv = __shfl_up_sync(0xffffffffu, inc, off);
        if (lane >= off) inc += vv;
    }
    if (lane == 31) wsum[wd] = inc;
    __syncthreads();
    if (tid < 8) {
        unsigned vv = wsum[tid], s2 = vv;
        #pragma unroll
        for (int off = 1; off < 8; off <<= 1) {
            unsigned w2 = __shfl_up_sync(0xffu, s2, off);
            if (tid >= off) s2 += w2;
        }
        wsum[tid] = s2 - vv;
    }
    __syncthreads();
    unsigned ex = inc - pk + wsum[wd];
    unsigned gt_run = ex >> 16, eq_run = ex & 0xffff;
    #pragma unroll
    for (int i = 0; i < 16; i++) {
        int t = base + i;
        unsigned uu = su[t];
        if (uu > ustar) {
            g_idx[b * K_ + gt_run + min(eq_run, r)] = t;
            gt_run++;
        } else if (uu == ustar) {
            if (eq_run < r) g_idx[b * K_ + gt_run + eq_run] = t;
            eq_run++;
        }
    }
}

// ---------------------------------------------------------------------------
// k4: gather pooled rows (float4), 2 rows per 256-thread block
// ---------------------------------------------------------------------------
__global__ __launch_bounds__(256) void k4_gather(
    const float* __restrict__ emb, float* __restrict__ pooled)
{
    int bk = blockIdx.x * 2 + (threadIdx.x >> 7);
    int l  = threadIdx.x & 127;
    int b  = bk >> 9;
    int t  = g_idx[bk];
    const float4* src = (const float4*)(emb + (size_t)(b * T_ + t) * E_);
    float4* dst = (float4*)(pooled + (size_t)bk * E_);
    dst[l] = src[l];
}

// ---------------------------------------------------------------------------
extern "C" void kernel_launch(void* const* d_in, const int* in_sizes, int n_in,
                              void* d_out, int out_size)
{
    // handle possible dropped bool padding_mask (slots shift by one)
    int s = (in_sizes[2] == E_ * R_) ? -1 : 0;

    const float* emb   = (const float*)d_in[0];
    const float* ssfx  = (const float*)d_in[1];
    const float* W1    = (const float*)d_in[3 + s];
    const float* b1    = (const float*)d_in[4 + s];
    const float* ln_g  = (const float*)d_in[5 + s];
    const float* ln_b  = (const float*)d_in[6 + s];
    const float* convw = (const float*)d_in[7 + s];
    const float* convb = (const float*)d_in[8 + s];
    const float* ssfw  = (const float*)d_in[9 + s];
    const float* ssfb  = (const float*)d_in[10 + s];
    const float* gate  = (const float*)d_in[11 + s];

    const long long PO = (long long)B_ * K_ * E_;
    const long long AT = (long long)B_ * T_;

    float* pooled = (float*)d_out;
    float* attn = (out_size >= PO + AT) ? ((float*)d_out + PO) : nullptr;

    k0_prep<<<32, 256>>>(W1);
    k1_mma<<<(B_ * T_) / 128, 256>>>(emb, b1, ln_g, ln_b, convw);
    k3_score_topk<<<B_, 256>>>(ssfx, convb, ssfw, ssfb, gate, attn);
    k4_gather<<<(B_ * K_) / 2, 256>>>(emb, pooled);
}